// round 11
// baseline (speedup 1.0000x reference)
#include <cuda_runtime.h>
#include <cuda_bf16.h>

// embeddings [B=512, I=128, D=64] fp32
// out[b,i,d] = tanh( emb[b,i,d] * (1/I) * sum_j emb[b,j,d] )
//
// R11: R2 lane layout + INTRA-CTA cross-iteration pipelining.
// Grid 256 x 256 thr; each CTA processes 4 chunks (chunk = 8-f4-column
// half-batch, as in R2). In iteration i the 4 independent LDG.128 for
// chunk i+1 are issued BEFORE the reduce/barrier/tanh/store phase of
// chunk i, so the next DRAM round-trip overlaps the current serial
// chain (phase-sum -> phase-max, no wave-transition cost, unlike R10).

static constexpr int BATCH   = 512;
static constexpr int SEQ_I   = 128;
static constexpr int F4_ROW  = 16;       // 64 floats / 4
static constexpr int F4_COLS = 8;        // f4 columns per chunk
static constexpr int THREADS = 256;
static constexpr int GRID    = 256;
static constexpr int ITERS   = 4;        // 1024 chunks / 256 CTAs

__device__ __forceinline__ float fast_tanh(float x) {
    float y;
    asm("tanh.approx.f32 %0, %1;" : "=f"(y) : "f"(x));
    return y;
}

__global__ __launch_bounds__(THREADS, 8)
void ATT0_40707700032104_kernel(const float4* __restrict__ in,
                                float4* __restrict__ out) {
    const int t    = threadIdx.x;
    const int c    = t & (F4_COLS - 1);   // f4 column in chunk (0..7)
    const int rg   = t >> 3;              // base row (0..31)
    const int lane = t & 31;
    const int w    = t >> 5;              // warp id (0..7)

    __shared__ float4 wsum[8][F4_COLS];
    __shared__ float4 mean4[F4_COLS];

    // chunk id = blockIdx.x + GRID*it ; batch = chunk>>1, half = chunk&1
    auto chunk_base = [&](int chunk) -> size_t {
        return (size_t)(chunk >> 1) * (SEQ_I * F4_ROW)
             + (size_t)(chunk & 1) * F4_COLS + c;
    };

    // ---- Prologue: load chunk 0 ----
    float4 v[4], vn[4];
    {
        const float4* src = in + chunk_base(blockIdx.x);
#pragma unroll
        for (int k = 0; k < 4; k++)
            v[k] = src[(size_t)(rg + 32 * k) * F4_ROW];
    }

#pragma unroll
    for (int it = 0; it < ITERS; it++) {
        const int chunk = blockIdx.x + GRID * it;
        const size_t base = chunk_base(chunk);

        // ---- Prefetch next chunk BEFORE the serial phase ----
        if (it < ITERS - 1) {
            const float4* nsrc = in + chunk_base(chunk + GRID);
#pragma unroll
            for (int k = 0; k < 4; k++)
                vn[k] = nsrc[(size_t)(rg + 32 * k) * F4_ROW];
        }

        // ---- Per-thread column partial ----
        float4 s;
        s.x = (v[0].x + v[1].x) + (v[2].x + v[3].x);
        s.y = (v[0].y + v[1].y) + (v[2].y + v[3].y);
        s.z = (v[0].z + v[1].z) + (v[2].z + v[3].z);
        s.w = (v[0].w + v[1].w) + (v[2].w + v[3].w);

        // ---- Warp reduce: lanes l, l+8, l+16, l+24 share column c ----
#pragma unroll
        for (int off = 8; off <= 16; off <<= 1) {
            s.x += __shfl_xor_sync(0xffffffffu, s.x, off);
            s.y += __shfl_xor_sync(0xffffffffu, s.y, off);
            s.z += __shfl_xor_sync(0xffffffffu, s.z, off);
            s.w += __shfl_xor_sync(0xffffffffu, s.w, off);
        }

        // ---- Cross-warp reduce via 8x8 smem stage ----
        if (lane < F4_COLS) wsum[w][lane] = s;
        __syncthreads();

        if (t < F4_COLS) {
            float4 m = wsum[0][t];
#pragma unroll
            for (int ww = 1; ww < 8; ww++) {
                float4 p = wsum[ww][t];
                m.x += p.x; m.y += p.y; m.z += p.z; m.w += p.w;
            }
            const float inv = 1.0f / (float)SEQ_I;
            m.x *= inv; m.y *= inv; m.z *= inv; m.w *= inv;
            mean4[t] = m;
        }
        __syncthreads();

        const float4 m = mean4[c];

        // ---- tanh(v * mean), 4 coalesced STG.128 ----
        float4* dst = out + base;
#pragma unroll
        for (int k = 0; k < 4; k++) {
            float4 r;
            r.x = fast_tanh(v[k].x * m.x);
            r.y = fast_tanh(v[k].y * m.y);
            r.z = fast_tanh(v[k].z * m.z);
            r.w = fast_tanh(v[k].w * m.w);
            dst[(size_t)(rg + 32 * k) * F4_ROW] = r;
        }

        // ---- Rotate pipeline ----
        if (it < ITERS - 1) {
#pragma unroll
            for (int k = 0; k < 4; k++) v[k] = vn[k];
        }
    }
}

extern "C" void kernel_launch(void* const* d_in, const int* in_sizes, int n_in,
                              void* d_out, int out_size) {
    const float4* in  = (const float4*)d_in[0];
    float4*       out = (float4*)d_out;
    ATT0_40707700032104_kernel<<<GRID, THREADS>>>(in, out);
}